// round 16
// baseline (speedup 1.0000x reference)
#include <cuda_runtime.h>
#include <cuda_bf16.h>
#include <cuda_fp16.h>
#include <cstdint>
#include <cstring>

#define Nn 1024
#define Mm 256
#define Bb 1024
#define Kk 1280
#define TMt 128           // CTA tile rows
#define TNt 32            // CTA tile cols
#define TKt 32            // K per staged tile
#define NTIL 40           // 8 W2 tiles then 32 Toeplitz tiles
#define BETA 0.01f
#define EPSL 1e-12f
#define THREADS 128       // 4 warps, 32x32 warp tiles (4x1)

typedef uint32_t u32;

// A ring: 16 m16-slots. Slot = 2 fp16 planes (r,i) x [ks 0..1][lane][16B]
//   slot stride 2048, plane stride 1024, ks stride 512.
// B: double buffer, 2 planes (r,i) x [n8-pair 0..1][ks][lane][16B], plane 2048.
#define SLOT 2048
#define RINGB (16 * SLOT)          // 32768
#define BBUF 4096
#define SMTOT (RINGB + 2 * BBUF)   // 40960

static __device__ __forceinline__ u32 pk16(float a, float b) {
    __half2 t = __floats2half2_rn(a, b);
    u32 h; memcpy(&h, &t, 4); return h;
}
static __device__ __forceinline__ u32 h2add(u32 a, u32 b) {
    __half2 x, y; memcpy(&x, &a, 4); memcpy(&y, &b, 4);
    __half2 r = __hadd2(x, y); u32 d; memcpy(&d, &r, 4); return d;
}
static __device__ __forceinline__ uint4 h2add4(const uint4& a, const uint4& b) {
    uint4 r;
    r.x = h2add(a.x, b.x); r.y = h2add(a.y, b.y);
    r.z = h2add(a.z, b.z); r.w = h2add(a.w, b.w);
    return r;
}
static __device__ __forceinline__ u32 smem_u32(const void* p) {
    u32 a;
    asm("{ .reg .u64 t; cvta.to.shared.u64 t, %1; cvt.u32.u64 %0, t; }" : "=r"(a) : "l"(p));
    return a;
}
static __device__ __forceinline__ uint4 lds128(u32 addr) {
    uint4 r;
    asm volatile("ld.shared.v4.b32 {%0,%1,%2,%3}, [%4];"
                 : "=r"(r.x), "=r"(r.y), "=r"(r.z), "=r"(r.w) : "r"(addr));
    return r;
}
static __device__ __forceinline__ void mma16816(float* c, const uint4& a, u32 b0, u32 b1) {
    asm volatile(
        "mma.sync.aligned.m16n8k16.row.col.f32.f16.f16.f32 "
        "{%0,%1,%2,%3}, {%4,%5,%6,%7}, {%8,%9}, {%0,%1,%2,%3};"
        : "+f"(c[0]), "+f"(c[1]), "+f"(c[2]), "+f"(c[3])
        : "r"(a.x), "r"(a.y), "r"(a.z), "r"(a.w), "r"(b0), "r"(b1));
}

// k0 of schedule index i: W2 region first (i<8), then Toeplitz ascending.
static __device__ __forceinline__ int k0_of(int i) {
    return (i < 8) ? (1024 + i * 32) : ((i - 8) * 32);
}
// ring slot of m16-tile j for schedule index i
static __device__ __forceinline__ int slot_of(int i, int j) {
    return (i < 8) ? (8 * (i & 1) + j) : ((j - 2 * (i - 8)) & 15);
}
// within-(slot,plane) offset for value (nl in 0..15, kp in 0..15)  [proven map]
static __device__ __forceinline__ u32 inner_a(int nl, int kp) {
    int kpp = kp & 7;
    return (u32)((kp >> 3) * 512 + (((nl & 7) * 4 + (kpp & 3)) * 16) +
                 (((kpp >= 4) ? 2 : 0) + (nl >> 3)) * 4);
}
// within-plane offset for B value (c in 0..31, kp in 0..15)  [proven map]
static __device__ __forceinline__ u32 off_b(int c, int kp) {
    int kpp = kp & 7;
    return (u32)((c >> 4) * 1024 + (kp >> 3) * 512 +
                 (((c & 7) * 4 + (kpp & 3)) * 16) +
                 ((((c >> 3) & 1) * 2) + ((kpp >= 4) ? 1 : 0)) * 4);
}

// z = softthresh(W1 @ x + W2 @ y); W1[n,k]=v[N-1+n-k].
// Plain fp16 + Gauss 3-product; A-ring; 128x32 tiles -> 256 CTAs, 2 CTAs/SM.
__global__ __launch_bounds__(THREADS, 2)
void toeplitz_hmma10_kernel(
    const float* __restrict__ v_re,  const float* __restrict__ v_im,
    const float* __restrict__ W2_re, const float* __restrict__ W2_im,
    const float* __restrict__ x_re,  const float* __restrict__ x_im,
    const float* __restrict__ y_re,  const float* __restrict__ y_im,
    void* __restrict__ out, int omode)
{
    extern __shared__ char smem[];
    const u32 smb = smem_u32(smem);
    const int tid = threadIdx.x;
    const int wid = tid >> 5;                 // warp row (0..3), warp tile 32x32
    const int lid = tid & 31;
    const int r4 = lid >> 2;
    const int c2 = (lid & 3) * 2;
    const int row0 = blockIdx.y * TMt;
    const int col0 = blockIdx.x * TNt;
    const u32 lane16 = (u32)(lid * 16);

    float acc[3][2][4][4];
    #pragma unroll
    for (int p = 0; p < 3; ++p)
        #pragma unroll
        for (int mt = 0; mt < 2; ++mt)
            #pragma unroll
            for (int nt = 0; nt < 4; ++nt)
                #pragma unroll
                for (int q = 0; q < 4; ++q) acc[p][mt][nt][q] = 0.0f;

    // staging regs: full-A tiles need 16 items/thread, incremental 4, B 4.
    float Ar0[16], Ar1[16], Ai0[16], Ai1[16];
    float Br0[4], Br1[4], Bi0[4], Bi1[4];

    auto load_regs = [&](int i) {
        const int k0 = k0_of(i);
        if (i <= 8) {
            if (i < 8) {
                #pragma unroll
                for (int it = 0; it < 16; ++it) {
                    int idx = tid + it * THREADS;     // 0..2047
                    int kp = idx & 15, n = idx >> 4;
                    int g = (row0 + n) * Mm + (k0 - Nn + 2 * kp);
                    Ar0[it] = W2_re[g]; Ar1[it] = W2_re[g + 1];
                    Ai0[it] = W2_im[g]; Ai1[it] = W2_im[g + 1];
                }
            } else {
                #pragma unroll
                for (int it = 0; it < 16; ++it) {
                    int idx = tid + it * THREADS;
                    int kp = idx & 15, n = idx >> 4;
                    int g = 1023 + (row0 + n) - (k0 + 2 * kp);
                    Ar0[it] = v_re[g]; Ar1[it] = v_re[g - 1];
                    Ai0[it] = v_im[g]; Ai1[it] = v_im[g - 1];
                }
            }
        } else {
            #pragma unroll
            for (int it = 0; it < 4; ++it) {
                int idx = tid + it * THREADS;         // 0..511, n in 0..31
                int kp = idx & 15, n = idx >> 4;
                int g = 1023 + (row0 + n) - (k0 + 2 * kp);
                Ar0[it] = v_re[g]; Ar1[it] = v_re[g - 1];
                Ai0[it] = v_im[g]; Ai1[it] = v_im[g - 1];
            }
        }
        const float* sr = (k0 < Nn) ? x_re : y_re;
        const float* si = (k0 < Nn) ? x_im : y_im;
        const int kb = (k0 < Nn) ? k0 : (k0 - Nn);
        #pragma unroll
        for (int it = 0; it < 4; ++it) {
            int idx = tid + it * THREADS;             // 0..511
            int cc = idx & 31, kp = idx >> 5;
            int g = (kb + 2 * kp) * Bb + col0 + cc;
            Br0[it] = sr[g]; Br1[it] = sr[g + Bb];
            Bi0[it] = si[g]; Bi1[it] = si[g + Bb];
        }
    };

    auto store_A_item = [&](int i, int it, int idx) {
        int kp = idx & 15, n = idx >> 4;
        char* sb = smem + slot_of(i, n >> 4) * SLOT;
        const u32 o = inner_a(n & 15, kp);
        *(u32*)(sb + o)        = pk16(Ar0[it], Ar1[it]);
        *(u32*)(sb + 1024 + o) = pk16(Ai0[it], Ai1[it]);
    };

    auto store_smem = [&](int i) {
        if (i <= 8) {
            #pragma unroll
            for (int it = 0; it < 16; ++it) store_A_item(i, it, tid + it * THREADS);
        } else {
            #pragma unroll
            for (int it = 0; it < 4; ++it) store_A_item(i, it, tid + it * THREADS);
        }
        char* Bp = smem + RINGB + (i & 1) * BBUF;
        #pragma unroll
        for (int it = 0; it < 4; ++it) {
            int idx = tid + it * THREADS;
            const u32 o = off_b(idx & 31, idx >> 5);
            *(u32*)(Bp + o)        = pk16(Br0[it], Br1[it]);
            *(u32*)(Bp + 2048 + o) = pk16(Bi0[it], Bi1[it]);
        }
    };

    load_regs(0);
    store_smem(0);
    __syncthreads();

    for (int i = 0; i < NTIL; ++i) {
        if (i + 1 < NTIL) load_regs(i + 1);

        const u32 s0 = smb + (u32)(slot_of(i, wid * 2) * SLOT);
        const u32 s1 = smb + (u32)(slot_of(i, wid * 2 + 1) * SLOT);
        const u32 bb = smb + RINGB + (u32)((i & 1) * BBUF);
        #pragma unroll
        for (int ks = 0; ks < 2; ++ks) {
            const u32 ko = (u32)(ks * 512) + lane16;
            // planes p: 0=r, 1=i, 2=s(computed in regs)
            uint4 AH[3][2], BH[3][2];
            AH[0][0] = lds128(s0 + ko);         AH[0][1] = lds128(s1 + ko);
            AH[1][0] = lds128(s0 + 1024 + ko);  AH[1][1] = lds128(s1 + 1024 + ko);
            BH[0][0] = lds128(bb + ko);         BH[0][1] = lds128(bb + 1024 + ko);
            BH[1][0] = lds128(bb + 2048 + ko);  BH[1][1] = lds128(bb + 3072 + ko);
            #pragma unroll
            for (int mt = 0; mt < 2; ++mt) AH[2][mt] = h2add4(AH[0][mt], AH[1][mt]);
            #pragma unroll
            for (int nb = 0; nb < 2; ++nb) BH[2][nb] = h2add4(BH[0][nb], BH[1][nb]);
            #pragma unroll
            for (int p = 0; p < 3; ++p) {
                #pragma unroll
                for (int mt = 0; mt < 2; ++mt) {
                    mma16816(acc[p][mt][0], AH[p][mt], BH[p][0].x, BH[p][0].y);
                    mma16816(acc[p][mt][1], AH[p][mt], BH[p][0].z, BH[p][0].w);
                    mma16816(acc[p][mt][2], AH[p][mt], BH[p][1].x, BH[p][1].y);
                    mma16816(acc[p][mt][3], AH[p][mt], BH[p][1].z, BH[p][1].w);
                }
            }
        }

        if (i + 1 < NTIL) store_smem(i + 1);
        __syncthreads();
    }

    // ---- epilogue: re = P1-P2, im = P3-P1-P2, soft-threshold, store ----
    const int wm = wid * 32;
    #pragma unroll
    for (int mt = 0; mt < 2; ++mt) {
        #pragma unroll
        for (int nt = 0; nt < 4; ++nt) {
            #pragma unroll
            for (int half = 0; half < 2; ++half) {
                const int q0 = half * 2;
                const int row = row0 + wm + mt * 16 + r4 + half * 8;
                const int col = col0 + nt * 8 + c2;
                float p1a = acc[0][mt][nt][q0],     p1b = acc[0][mt][nt][q0 + 1];
                float p2a = acc[1][mt][nt][q0],     p2b = acc[1][mt][nt][q0 + 1];
                float p3a = acc[2][mt][nt][q0],     p3b = acc[2][mt][nt][q0 + 1];
                float rea = p1a - p2a,  reb = p1b - p2b;
                float ima = p3a - p1a - p2a, imb = p3b - p1b - p2b;
                float maga = sqrtf(rea * rea + ima * ima);
                float sca  = fmaxf(maga - BETA, 0.0f) / fmaxf(maga, EPSL);
                float magb = sqrtf(reb * reb + imb * imb);
                float scb  = fmaxf(magb - BETA, 0.0f) / fmaxf(magb, EPSL);
                rea *= sca; ima *= sca; reb *= scb; imb *= scb;
                const int e = row * Bb + col;
                if (omode == 0) {
                    __nv_bfloat162 pa = __floats2bfloat162_rn(rea, ima);
                    __nv_bfloat162 pb = __floats2bfloat162_rn(reb, imb);
                    u32 ua, ub; memcpy(&ua, &pa, 4); memcpy(&ub, &pb, 4);
                    *(uint2*)((u32*)out + e) = make_uint2(ua, ub);
                } else {
                    *(float2*)((float*)out + e) = make_float2(rea, reb);
                }
            }
        }
    }
}

extern "C" void kernel_launch(void* const* d_in, const int* in_sizes, int n_in,
                              void* d_out, int out_size) {
    // Crash-proof input dispatch: classify by element count (elements or bytes).
    int scale = 1;
    bool have2047 = false, have8188 = false;
    for (int i = 0; i < n_in && i < 8; ++i) {
        if (in_sizes[i] == 2 * Nn - 1) have2047 = true;
        if (in_sizes[i] == (2 * Nn - 1) * 4) have8188 = true;
    }
    if (!have2047 && have8188) scale = 4;

    const float* vp[2] = {0, 0};
    const float* xp[2] = {0, 0};
    const float* mp[4] = {0, 0, 0, 0};
    int nv = 0, nx = 0, nm = 0;
    for (int i = 0; i < n_in && i < 8; ++i) {
        const float* p = (const float*)d_in[i];
        long s = in_sizes[i];
        if (s == (long)(2 * Nn - 1) * scale)      { if (nv < 2) vp[nv++] = p; }
        else if (s == (long)Nn * Bb * scale)      { if (nx < 2) xp[nx++] = p; }
        else if (s == (long)Nn * Mm * scale)      { if (nm < 4) mp[nm++] = p; }
    }
    const float* v_re  = vp[0] ? vp[0] : (const float*)d_in[0];
    const float* v_im  = vp[1] ? vp[1] : (const float*)d_in[1];
    const float* W2_re = mp[0] ? mp[0] : (const float*)d_in[2];
    const float* W2_im = mp[1] ? mp[1] : (const float*)d_in[3];
    const float* x_re  = xp[0] ? xp[0] : (const float*)d_in[4];
    const float* x_im  = xp[1] ? xp[1] : (const float*)d_in[5];
    const float* y_re  = mp[2] ? mp[2] : (const float*)d_in[6];
    const float* y_im  = mp[3] ? mp[3] : (const float*)d_in[7];

    const int omode = (out_size >= 2 * Nn * Bb) ? 0 : 1;

    cudaFuncSetAttribute(toeplitz_hmma10_kernel,
                         cudaFuncAttributeMaxDynamicSharedMemorySize, SMTOT);
    dim3 grid(Bb / TNt, Nn / TMt);   // (32, 8) = 256 CTAs, 2/SM
    toeplitz_hmma10_kernel<<<grid, THREADS, SMTOT>>>(
        v_re, v_im, W2_re, W2_im, x_re, x_im, y_re, y_im,
        d_out, omode);
}

// round 17
// speedup vs baseline: 1.0410x; 1.0410x over previous
#include <cuda_runtime.h>
#include <cuda_bf16.h>
#include <cuda_fp16.h>
#include <cstdint>
#include <cstring>

#define Nn 1024
#define Mm 256
#define Bb 1024
#define Kk 1280
#define TMt 128           // CTA tile rows
#define TNt 64            // CTA tile cols
#define TKt 64            // K per staged tile (doubled)
#define NTIL 20           // 4 W2 tiles then 16 Toeplitz tiles
#define BETA 0.01f
#define EPSL 1e-12f
#define THREADS 256

typedef uint32_t u32;

// A ring: 16 m16-slots. Slot = 2 fp16 planes (r,i) x [ks 0..3][lane][16B]
//   slot stride 4096, plane stride 2048, ks stride 512.
// B: double buffer, 2 planes (r,i); plane = [n8-pair 0..3][ks 0..3][lane][16B] = 8192.
#define SLOT 4096
#define RINGB (16 * SLOT)          // 65536
#define BBUF 16384
#define SMTOT (RINGB + 2 * BBUF)   // 98304

static __device__ __forceinline__ u32 pk16(float a, float b) {
    __half2 t = __floats2half2_rn(a, b);
    u32 h; memcpy(&h, &t, 4); return h;
}
static __device__ __forceinline__ u32 h2add(u32 a, u32 b) {
    __half2 x, y; memcpy(&x, &a, 4); memcpy(&y, &b, 4);
    __half2 r = __hadd2(x, y); u32 d; memcpy(&d, &r, 4); return d;
}
static __device__ __forceinline__ uint4 h2add4(const uint4& a, const uint4& b) {
    uint4 r;
    r.x = h2add(a.x, b.x); r.y = h2add(a.y, b.y);
    r.z = h2add(a.z, b.z); r.w = h2add(a.w, b.w);
    return r;
}
static __device__ __forceinline__ u32 smem_u32(const void* p) {
    u32 a;
    asm("{ .reg .u64 t; cvta.to.shared.u64 t, %1; cvt.u32.u64 %0, t; }" : "=r"(a) : "l"(p));
    return a;
}
static __device__ __forceinline__ uint4 lds128(u32 addr) {
    uint4 r;
    asm volatile("ld.shared.v4.b32 {%0,%1,%2,%3}, [%4];"
                 : "=r"(r.x), "=r"(r.y), "=r"(r.z), "=r"(r.w) : "r"(addr));
    return r;
}
static __device__ __forceinline__ void mma16816(float* c, const uint4& a, u32 b0, u32 b1) {
    asm volatile(
        "mma.sync.aligned.m16n8k16.row.col.f32.f16.f16.f32 "
        "{%0,%1,%2,%3}, {%4,%5,%6,%7}, {%8,%9}, {%0,%1,%2,%3};"
        : "+f"(c[0]), "+f"(c[1]), "+f"(c[2]), "+f"(c[3])
        : "r"(a.x), "r"(a.y), "r"(a.z), "r"(a.w), "r"(b0), "r"(b1));
}

// k0 of schedule index i: W2 region first (i<4), then Toeplitz ascending.
static __device__ __forceinline__ int k0_of(int i) {
    return (i < 4) ? (1024 + i * 64) : ((i - 4) * 64);
}
// ring slot of m16-tile j for schedule index i (shift 4/tile in Toeplitz)
static __device__ __forceinline__ int slot_of(int i, int j) {
    return (i < 4) ? (8 * (i & 1) + j) : ((j - 4 * (i - 4)) & 15);
}
// within-(slot,plane) offset for value (nl 0..15, kp 0..31)
static __device__ __forceinline__ u32 inner_a(int nl, int kp) {
    int kpp = kp & 7;
    return (u32)((kp >> 3) * 512 + (((nl & 7) * 4 + (kpp & 3)) * 16) +
                 (((kpp >= 4) ? 2 : 0) + (nl >> 3)) * 4);
}
// within-plane offset for B value (c 0..63, kp 0..31)
static __device__ __forceinline__ u32 off_b(int c, int kp) {
    int kpp = kp & 7;
    return (u32)((c >> 4) * 2048 + (kp >> 3) * 512 +
                 (((c & 7) * 4 + (kpp & 3)) * 16) +
                 ((((c >> 3) & 1) * 2) + ((kpp >= 4) ? 1 : 0)) * 4);
}

// z = softthresh(W1 @ x + W2 @ y); W1[n,k]=v[N-1+n-k].
// Plain fp16 + Gauss 3-product; A-ring; 64-K tiles (half the barriers).
__global__ __launch_bounds__(THREADS, 1)
void toeplitz_hmma11_kernel(
    const float* __restrict__ v_re,  const float* __restrict__ v_im,
    const float* __restrict__ W2_re, const float* __restrict__ W2_im,
    const float* __restrict__ x_re,  const float* __restrict__ x_im,
    const float* __restrict__ y_re,  const float* __restrict__ y_im,
    void* __restrict__ out, int omode)
{
    extern __shared__ char smem[];
    const u32 smb = smem_u32(smem);
    const int tid = threadIdx.x;
    const int wid = tid >> 5;
    const int lid = tid & 31;
    const int wr = wid >> 1, wc = wid & 1;    // 4x2 warp grid, warp tile 32x32
    const int r4 = lid >> 2;
    const int c2 = (lid & 3) * 2;
    const int row0 = blockIdx.y * TMt;
    const int col0 = blockIdx.x * TNt;
    const u32 lane16 = (u32)(lid * 16);

    float acc[3][2][4][4];
    #pragma unroll
    for (int p = 0; p < 3; ++p)
        #pragma unroll
        for (int mt = 0; mt < 2; ++mt)
            #pragma unroll
            for (int nt = 0; nt < 4; ++nt)
                #pragma unroll
                for (int q = 0; q < 4; ++q) acc[p][mt][nt][q] = 0.0f;

    // staging regs: full-A tiles 16 items, incremental 8, B 8.
    float Ar0[16], Ar1[16], Ai0[16], Ai1[16];
    float Br0[8], Br1[8], Bi0[8], Bi1[8];

    auto load_regs = [&](int i) {
        const int k0 = k0_of(i);
        if (i <= 4) {
            if (i < 4) {
                #pragma unroll
                for (int it = 0; it < 16; ++it) {
                    int idx = tid + it * THREADS;     // 0..4095
                    int kp = idx & 31, n = idx >> 5;
                    int g = (row0 + n) * Mm + (k0 - Nn + 2 * kp);
                    Ar0[it] = W2_re[g]; Ar1[it] = W2_re[g + 1];
                    Ai0[it] = W2_im[g]; Ai1[it] = W2_im[g + 1];
                }
            } else {
                #pragma unroll
                for (int it = 0; it < 16; ++it) {
                    int idx = tid + it * THREADS;
                    int kp = idx & 31, n = idx >> 5;
                    int g = 1023 + (row0 + n) - (k0 + 2 * kp);
                    Ar0[it] = v_re[g]; Ar1[it] = v_re[g - 1];
                    Ai0[it] = v_im[g]; Ai1[it] = v_im[g - 1];
                }
            }
        } else {
            #pragma unroll
            for (int it = 0; it < 8; ++it) {
                int idx = tid + it * THREADS;         // 0..2047, n in 0..63
                int kp = idx & 31, n = idx >> 5;
                int g = 1023 + (row0 + n) - (k0 + 2 * kp);
                Ar0[it] = v_re[g]; Ar1[it] = v_re[g - 1];
                Ai0[it] = v_im[g]; Ai1[it] = v_im[g - 1];
            }
        }
        const float* sr = (k0 < Nn) ? x_re : y_re;
        const float* si = (k0 < Nn) ? x_im : y_im;
        const int kb = (k0 < Nn) ? k0 : (k0 - Nn);
        #pragma unroll
        for (int it = 0; it < 8; ++it) {
            int idx = tid + it * THREADS;             // 0..2047
            int cc = idx & 63, kp = idx >> 6;         // kp 0..31
            int g = (kb + 2 * kp) * Bb + col0 + cc;
            Br0[it] = sr[g]; Br1[it] = sr[g + Bb];
            Bi0[it] = si[g]; Bi1[it] = si[g + Bb];
        }
    };

    auto store_A_item = [&](int i, int it, int idx) {
        int kp = idx & 31, n = idx >> 5;
        char* sb = smem + slot_of(i, n >> 4) * SLOT;
        const u32 o = inner_a(n & 15, kp);
        *(u32*)(sb + o)        = pk16(Ar0[it], Ar1[it]);
        *(u32*)(sb + 2048 + o) = pk16(Ai0[it], Ai1[it]);
    };

    auto store_smem = [&](int i) {
        if (i <= 4) {
            #pragma unroll
            for (int it = 0; it < 16; ++it) store_A_item(i, it, tid + it * THREADS);
        } else {
            #pragma unroll
            for (int it = 0; it < 8; ++it) store_A_item(i, it, tid + it * THREADS);
        }
        char* Bp = smem + RINGB + (i & 1) * BBUF;
        #pragma unroll
        for (int it = 0; it < 8; ++it) {
            int idx = tid + it * THREADS;
            const u32 o = off_b(idx & 63, idx >> 6);
            *(u32*)(Bp + o)        = pk16(Br0[it], Br1[it]);
            *(u32*)(Bp + 8192 + o) = pk16(Bi0[it], Bi1[it]);
        }
    };

    load_regs(0);
    store_smem(0);
    __syncthreads();

    for (int i = 0; i < NTIL; ++i) {
        if (i + 1 < NTIL) load_regs(i + 1);

        const u32 s0 = smb + (u32)(slot_of(i, wr * 2) * SLOT);
        const u32 s1 = smb + (u32)(slot_of(i, wr * 2 + 1) * SLOT);
        const u32 bb = smb + RINGB + (u32)((i & 1) * BBUF);
        const u32 bn0 = (u32)(wc * 2 * 2048), bn1 = bn0 + 2048;
        #pragma unroll
        for (int ks = 0; ks < 4; ++ks) {
            const u32 ko = (u32)(ks * 512) + lane16;
            // planes p: 0=r, 1=i, 2=s(computed in regs)
            uint4 AH[3][2], BH[3][2];
            AH[0][0] = lds128(s0 + ko);         AH[0][1] = lds128(s1 + ko);
            AH[1][0] = lds128(s0 + 2048 + ko);  AH[1][1] = lds128(s1 + 2048 + ko);
            BH[0][0] = lds128(bb + bn0 + ko);   BH[0][1] = lds128(bb + bn1 + ko);
            BH[1][0] = lds128(bb + 8192 + bn0 + ko);
            BH[1][1] = lds128(bb + 8192 + bn1 + ko);
            #pragma unroll
            for (int mt = 0; mt < 2; ++mt) AH[2][mt] = h2add4(AH[0][mt], AH[1][mt]);
            #pragma unroll
            for (int nb = 0; nb < 2; ++nb) BH[2][nb] = h2add4(BH[0][nb], BH[1][nb]);
            #pragma unroll
            for (int p = 0; p < 3; ++p) {
                #pragma unroll
                for (int mt = 0; mt < 2; ++mt) {
                    mma16816(acc[p][mt][0], AH[p][mt], BH[p][0].x, BH[p][0].y);
                    mma16816(acc[p][mt][1], AH[p][mt], BH[p][0].z, BH[p][0].w);
                    mma16816(acc[p][mt][2], AH[p][mt], BH[p][1].x, BH[p][1].y);
                    mma16816(acc[p][mt][3], AH[p][mt], BH[p][1].z, BH[p][1].w);
                }
            }
        }

        if (i + 1 < NTIL) store_smem(i + 1);
        __syncthreads();
    }

    // ---- epilogue: re = P1-P2, im = P3-P1-P2, soft-threshold, store ----
    const int wm = wr * 32, wn = wc * 32;
    #pragma unroll
    for (int mt = 0; mt < 2; ++mt) {
        #pragma unroll
        for (int nt = 0; nt < 4; ++nt) {
            #pragma unroll
            for (int half = 0; half < 2; ++half) {
                const int q0 = half * 2;
                const int row = row0 + wm + mt * 16 + r4 + half * 8;
                const int col = col0 + wn + nt * 8 + c2;
                float p1a = acc[0][mt][nt][q0],     p1b = acc[0][mt][nt][q0 + 1];
                float p2a = acc[1][mt][nt][q0],     p2b = acc[1][mt][nt][q0 + 1];
                float p3a = acc[2][mt][nt][q0],     p3b = acc[2][mt][nt][q0 + 1];
                float rea = p1a - p2a,  reb = p1b - p2b;
                float ima = p3a - p1a - p2a, imb = p3b - p1b - p2b;
                float maga = sqrtf(rea * rea + ima * ima);
                float sca  = fmaxf(maga - BETA, 0.0f) / fmaxf(maga, EPSL);
                float magb = sqrtf(reb * reb + imb * imb);
                float scb  = fmaxf(magb - BETA, 0.0f) / fmaxf(magb, EPSL);
                rea *= sca; ima *= sca; reb *= scb; imb *= scb;
                const int e = row * Bb + col;
                if (omode == 0) {
                    __nv_bfloat162 pa = __floats2bfloat162_rn(rea, ima);
                    __nv_bfloat162 pb = __floats2bfloat162_rn(reb, imb);
                    u32 ua, ub; memcpy(&ua, &pa, 4); memcpy(&ub, &pb, 4);
                    *(uint2*)((u32*)out + e) = make_uint2(ua, ub);
                } else {
                    *(float2*)((float*)out + e) = make_float2(rea, reb);
                }
            }
        }
    }
}

extern "C" void kernel_launch(void* const* d_in, const int* in_sizes, int n_in,
                              void* d_out, int out_size) {
    // Crash-proof input dispatch: classify by element count (elements or bytes).
    int scale = 1;
    bool have2047 = false, have8188 = false;
    for (int i = 0; i < n_in && i < 8; ++i) {
        if (in_sizes[i] == 2 * Nn - 1) have2047 = true;
        if (in_sizes[i] == (2 * Nn - 1) * 4) have8188 = true;
    }
    if (!have2047 && have8188) scale = 4;

    const float* vp[2] = {0, 0};
    const float* xp[2] = {0, 0};
    const float* mp[4] = {0, 0, 0, 0};
    int nv = 0, nx = 0, nm = 0;
    for (int i = 0; i < n_in && i < 8; ++i) {
        const float* p = (const float*)d_in[i];
        long s = in_sizes[i];
        if (s == (long)(2 * Nn - 1) * scale)      { if (nv < 2) vp[nv++] = p; }
        else if (s == (long)Nn * Bb * scale)      { if (nx < 2) xp[nx++] = p; }
        else if (s == (long)Nn * Mm * scale)      { if (nm < 4) mp[nm++] = p; }
    }
    const float* v_re  = vp[0] ? vp[0] : (const float*)d_in[0];
    const float* v_im  = vp[1] ? vp[1] : (const float*)d_in[1];
    const float* W2_re = mp[0] ? mp[0] : (const float*)d_in[2];
    const float* W2_im = mp[1] ? mp[1] : (const float*)d_in[3];
    const float* x_re  = xp[0] ? xp[0] : (const float*)d_in[4];
    const float* x_im  = xp[1] ? xp[1] : (const float*)d_in[5];
    const float* y_re  = mp[2] ? mp[2] : (const float*)d_in[6];
    const float* y_im  = mp[3] ? mp[3] : (const float*)d_in[7];

    const int omode = (out_size >= 2 * Nn * Bb) ? 0 : 1;

    cudaFuncSetAttribute(toeplitz_hmma11_kernel,
                         cudaFuncAttributeMaxDynamicSharedMemorySize, SMTOT);
    dim3 grid(Bb / TNt, Nn / TMt);   // (16, 8) = 128 CTAs
    toeplitz_hmma11_kernel<<<grid, THREADS, SMTOT>>>(
        v_re, v_im, W2_re, W2_im, x_re, x_im, y_re, y_im,
        d_out, omode);
}